// round 4
// baseline (speedup 1.0000x reference)
#include <cuda_runtime.h>
#include <cstdint>

#define BB 16
#define TT 1024
#define HH 512
#define AA 80
#define UU 600
#define PP 30

// W duplicated for FFMA2 b-operands: g_W2[h][pg*8 + 2j + d] = W[h][pg*4+j]
__device__ __align__(16) float g_W2[HH * 64];

__global__ void k0_dupW(const float* __restrict__ W) {
    int idx = blockIdx.x * 256 + threadIdx.x;     // 128*256 = 32768
    int h = idx >> 6, c = idx & 63;
    int p = (c >> 3) * 4 + ((c & 7) >> 1);
    g_W2[idx] = (p < PP) ? W[h * PP + p] : 0.f;
}

#define FMA2(d, a, b) asm("fma.rn.f32x2 %0, %1, %2, %0;" : "+l"(d) : "l"(a), "l"(b))
#define ADD2(d, a)    asm("add.rn.f32x2 %0, %0, %1;" : "+l"(d) : "l"(a))
#define EX2A(d, a)    asm("ex2.approx.f32 %0, %1;" : "=f"(d) : "f"(a))

__device__ __forceinline__ void cpa16(uint32_t dst, const void* src) {
    asm volatile("cp.async.cg.shared.global [%0], [%1], 16;" :: "r"(dst), "l"(src));
}
#define CPA_COMMIT() asm volatile("cp.async.commit_group;")
#define CPA_WAIT0()  asm volatile("cp.async.wait_group 0;")

union F4U2  { float4 f4; unsigned long long u2[2]; };
union U64F2 { unsigned long long u; float2 f2; };

// smem layout (float offsets), all 16B-aligned
#define XT_OFF   0          // 2 * 64*68  = 8704
#define W2_OFF   8704       // 2 * 64*64  = 8192
#define CH_OFF   16896      // 2 * 16*80  = 2560
#define PH_OFF   19456      // 2 * 16*68  = 2176 (also reduction scratch, 2048)
#define ABK_OFF  21632      // 64*33      = 2112
#define UB_OFF   23744
#define SMEM_FLOATS 23748
#define SMEM_BYTES (SMEM_FLOATS * 4)

__global__ __launch_bounds__(256, 2) void fused(
    const float* __restrict__ lstm,
    const float* __restrict__ chs,
    const float* __restrict__ bias,
    float* __restrict__ out)
{
    extern __shared__ float S[];
    int* iUblk = (int*)&S[UB_OFF];
    const int tid  = threadIdx.x;
    const int row0 = blockIdx.x * 64;
    const int b    = blockIdx.x >> 4;
    const float* lbase = lstm + (size_t)row0 * HH;
    const float* cb    = chs + (size_t)b * UU * AA;
    const uint32_t sbase = (uint32_t)__cvta_generic_to_shared(S);

    if (tid == 0) *iUblk = 16;

    // GEMM1 roles: 4t x 4p per thread; warps 0-3 take h-half 0, warps 4-7 half 1
    const int tg   = tid & 15;
    const int pg   = (tid >> 4) & 7;
    const int half = tid >> 7;
    const int hlane = tid & 31, wq = tid >> 5;    // staging roles

    unsigned long long acc[2][4];
#pragma unroll
    for (int i = 0; i < 2; ++i)
#pragma unroll
        for (int j = 0; j < 4; ++j) acc[i][j] = 0ULL;

    float xr[4][4];   // reg staging: 4 (t-quad, h) slices per chunk

#define LDG_X(hc) do {                                                        \
    _Pragma("unroll")                                                         \
    for (int it = 0; it < 4; ++it) {                                          \
        int q = wq + 8 * (it & 1);                                            \
        int h = hlane + 32 * (it >> 1);                                       \
        const float* src = lbase + (size_t)(4 * q) * HH + (hc) * 64 + h;      \
        xr[it][0] = src[0 * HH]; xr[it][1] = src[1 * HH];                     \
        xr[it][2] = src[2 * HH]; xr[it][3] = src[3 * HH];                     \
    } } while (0)

#define STS_X(bsel) do {                                                      \
    float* xt_ = &S[XT_OFF + (bsel) * 4352];                                  \
    _Pragma("unroll")                                                         \
    for (int it = 0; it < 4; ++it) {                                          \
        int q = wq + 8 * (it & 1);                                            \
        int h = hlane + 32 * (it >> 1);                                       \
        *(float4*)&xt_[h * 68 + 4 * q] =                                      \
            make_float4(xr[it][0], xr[it][1], xr[it][2], xr[it][3]);          \
    } } while (0)

#define CPA_W2(hc, bsel) do {                                                 \
    uint32_t dst_ = sbase + (uint32_t)(W2_OFF + (bsel) * 4096) * 4u;          \
    const float* src_ = g_W2 + (hc) * 4096;                                   \
    _Pragma("unroll")                                                         \
    for (int i = 0; i < 4; ++i) {                                             \
        int g = tid + 256 * i;                                                \
        cpa16(dst_ + (uint32_t)g * 16u, src_ + g * 4);                        \
    } } while (0)

    // ---------------- prologue ----------------
    CPA_W2(0, 0);
    {   // prefetch char chunks 0+1 (2560 floats = 640 float4; u<32 < UU)
        uint32_t dst = sbase + (uint32_t)CH_OFF * 4u;
#pragma unroll
        for (int i = 0; i < 3; ++i) {
            int g = tid + 256 * i;
            if (g < 640) cpa16(dst + (uint32_t)g * 16u, cb + g * 4);
        }
    }
    CPA_COMMIT();
    LDG_X(0); STS_X(0);
    LDG_X(1);
    CPA_WAIT0();
    __syncthreads();

    // ---------------- GEMM1 pipeline (h-split across warp halves) ----------
#pragma unroll 1
    for (int hc = 0; hc < 8; ++hc) {
        const int bsel = hc & 1;
        if (hc + 1 < 8) { CPA_W2(hc + 1, bsel ^ 1); CPA_COMMIT(); STS_X(bsel ^ 1); }
        if (hc + 2 < 8) LDG_X(hc + 2);

        const float* xt = &S[XT_OFF + bsel * 4352 + half * 32 * 68];
        const float* w2 = &S[W2_OFF + bsel * 4096 + half * 32 * 64];
#pragma unroll 16
        for (int h = 0; h < 32; ++h) {
            F4U2 x;  x.f4  = *(const float4*)&xt[h * 68 + tg * 4];
            F4U2 wa; wa.f4 = *(const float4*)&w2[h * 64 + pg * 8];
            F4U2 wb; wb.f4 = *(const float4*)&w2[h * 64 + pg * 8 + 4];
            FMA2(acc[0][0], x.u2[0], wa.u2[0]);
            FMA2(acc[0][1], x.u2[0], wa.u2[1]);
            FMA2(acc[0][2], x.u2[0], wb.u2[0]);
            FMA2(acc[0][3], x.u2[0], wb.u2[1]);
            FMA2(acc[1][0], x.u2[1], wa.u2[0]);
            FMA2(acc[1][1], x.u2[1], wa.u2[1]);
            FMA2(acc[1][2], x.u2[1], wb.u2[0]);
            FMA2(acc[1][3], x.u2[1], wb.u2[1]);
        }
        if (hc + 1 < 8) CPA_WAIT0();
        __syncthreads();
    }

    // ---------------- reduce the two h-halves through smem -----------------
    {
        unsigned long long* red = (unsigned long long*)&S[PH_OFF];
        if (half == 1) {
            unsigned long long* d = &red[(tid & 127) * 8];
#pragma unroll
            for (int i = 0; i < 2; ++i)
#pragma unroll
                for (int j = 0; j < 4; ++j) d[i * 4 + j] = acc[i][j];
        }
        __syncthreads();
        if (half == 0) {
            const unsigned long long* d = &red[tid * 8];
#pragma unroll
            for (int i = 0; i < 2; ++i)
#pragma unroll
                for (int j = 0; j < 4; ++j) ADD2(acc[i][j], d[i * 4 + j]);
        }
        __syncthreads();
    }

    // ---------------- epilogue: exp -> sABK (low half only) ----------------
    float* sabk = &S[ABK_OFF];
    if (half == 0) {
#pragma unroll
        for (int j = 0; j < 4; ++j) {
            int p = pg * 4 + j;
            if (p < PP) {
                float bs = bias[p];
#pragma unroll
                for (int tp = 0; tp < 2; ++tp) {
                    U64F2 v; v.u = acc[tp][j];
                    int tl = 4 * tg + 2 * tp;
                    sabk[tl * 33 + p]       = __expf(v.f2.x + bs);
                    sabk[(tl + 1) * 33 + p] = __expf(v.f2.y + bs);
                }
            }
        }
    }
    __syncthreads();

    // ---------------- phi setup + cutoff ----------------
    const int tphi = tid & 63, uh = tid >> 6;     // uh 0..3, 4 u's each
    float ra[10], rbl[10], rk[10];
    float um = 1.f;
#pragma unroll
    for (int m = 0; m < 10; ++m) {
        float av = sabk[tphi * 33 + m];
        float bv = sabk[tphi * 33 + 10 + m];
        float kv = sabk[tphi * 33 + 20 + m];
        ra[m] = av; rk[m] = kv;
        um = fmaxf(um, kv + sqrtf(40.f / bv));
        rbl[m] = -1.4426950408889634f * bv;       // phi term = a * 2^(rbl*d^2)
    }
    if (uh == 0)
        atomicMax(iUblk, (int)fminf(ceilf(um) + 2.f, (float)UU));
    __syncthreads();
    const int Ublk = *iUblk;
    const int nch  = (Ublk + 15) >> 4;

    // ---------------- windowed phi + GEMM2 ----------------
    const int tg2 = tid & 31, ag = tid >> 5;      // 2t x 10a per thread
    float accO[2][10];
#pragma unroll
    for (int i = 0; i < 2; ++i)
#pragma unroll
        for (int j = 0; j < 10; ++j) accO[i][j] = 0.f;

#pragma unroll 1
    for (int c = 0; c < nch; ++c) {
        const int kb = c & 1;
        if (c >= 2) {   // rare slow path: stage char chunk c (clamped)
            for (int idx = tid; idx < 1280; idx += 256) {
                int u = idx / 80, a = idx - u * 80;
                int gu = c * 16 + u; if (gu >= UU) gu = UU - 1;
                S[CH_OFF + kb * 1280 + idx] = cb[gu * AA + a];
            }
        }
        float* sphi = &S[PH_OFF + kb * 1088];
#pragma unroll
        for (int r = 0; r < 4; ++r) {
            float uf = (float)(c * 16 + uh * 4 + r);
            float s = 0.f;
#pragma unroll
            for (int m = 0; m < 10; ++m) {
                float d = rk[m] - uf;
                float e; EX2A(e, rbl[m] * d * d);
                s = fmaf(ra[m], e, s);
            }
            sphi[(uh * 4 + r) * 68 + tphi] = s;
        }
        __syncthreads();

        const float* sch = &S[CH_OFF + kb * 1280];
#pragma unroll 4
        for (int u = 0; u < 16; ++u) {
            float2 ph = *(const float2*)&sphi[u * 68 + tg2 * 2];
            const float2* cp2 = (const float2*)&sch[u * 80 + ag * 10];
            float2 c01 = cp2[0], c23 = cp2[1], c45 = cp2[2], c67 = cp2[3], c89 = cp2[4];
            float cc[10] = {c01.x, c01.y, c23.x, c23.y, c45.x,
                            c45.y, c67.x, c67.y, c89.x, c89.y};
#pragma unroll
            for (int j = 0; j < 10; ++j) {
                accO[0][j] = fmaf(ph.x, cc[j], accO[0][j]);
                accO[1][j] = fmaf(ph.y, cc[j], accO[1][j]);
            }
        }
        // next iteration's sync orders buffer reuse (double-buffered)
    }

    // ---------------- store ----------------
#pragma unroll
    for (int i = 0; i < 2; ++i) {
        float* orow = out + (size_t)(row0 + tg2 * 2 + i) * AA + ag * 10;
#pragma unroll
        for (int j2 = 0; j2 < 5; ++j2)
            *(float2*)&orow[j2 * 2] = make_float2(accO[i][2 * j2], accO[i][2 * j2 + 1]);
    }
}

extern "C" void kernel_launch(void* const* d_in, const int* in_sizes, int n_in,
                              void* d_out, int out_size)
{
    const float* lstm = (const float*)d_in[0];  // [16,1024,512]
    const float* chs  = (const float*)d_in[1];  // [16,600,80]
    const float* W    = (const float*)d_in[2];  // [512,30]
    const float* bias = (const float*)d_in[3];  // [30]
    float* out = (float*)d_out;                 // [16,1024,80]
    (void)in_sizes; (void)n_in; (void)out_size;

    cudaFuncSetAttribute(fused, cudaFuncAttributeMaxDynamicSharedMemorySize, SMEM_BYTES);
    k0_dupW<<<128, 256>>>(W);
    fused<<<256, 256, SMEM_BYTES>>>(lstm, chs, bias, out);
}

// round 7
// speedup vs baseline: 1.5972x; 1.5972x over previous
#include <cuda_runtime.h>
#include <cuda_bf16.h>
#include <cstdint>

#define HH 512
#define AA 80
#define UU 600
#define PP 30

// W^T in ldmatrix-fragment order, bf16 hi/lo planes.
// half index: ((ktile*4 + plane*2 + mtile)*256) + mat*64 + row*8 + col
//   p = mtile*16 + (mat&1)*8 + row ; k = ktile*16 + ((mat>>1)&1)*8 + col
__device__ __align__(16) uint16_t g_Wf[32768];

__global__ void k0_prepW(const float* __restrict__ W) {
    int i = blockIdx.x * 256 + threadIdx.x;      // 128*256 = 32768
    int col = i & 7, row = (i >> 3) & 7, mat = (i >> 6) & 3;
    int mtile = (i >> 8) & 1, plane = (i >> 9) & 1, ktile = i >> 10;
    int p = mtile * 16 + (mat & 1) * 8 + row;
    int k = ktile * 16 + ((mat >> 1) & 1) * 8 + col;
    float w = (p < PP) ? W[k * PP + p] : 0.f;
    __nv_bfloat16 hi = __float2bfloat16(w);
    __nv_bfloat16 v  = plane ? __float2bfloat16(w - __bfloat162float(hi)) : hi;
    g_Wf[i] = *(uint16_t*)&v;
}

// ---------------- PTX helpers (all sm_80-compatible) ----------------
#define EX2A(d, a) asm("ex2.approx.f32 %0, %1;" : "=f"(d) : "f"(a))

__device__ __forceinline__ void cpa16(uint32_t dst, const void* src) {
    asm volatile("cp.async.cg.shared.global [%0], [%1], 16;" :: "r"(dst), "l"(src));
}
#define CPA_COMMIT() asm volatile("cp.async.commit_group;")
#define CPA_WAIT0()  asm volatile("cp.async.wait_group 0;")

__device__ __forceinline__ uint32_t cvt_pack_bf2(float lo_elem, float hi_elem) {
    uint32_t r;
    asm("cvt.rn.bf16x2.f32 %0, %1, %2;" : "=r"(r) : "f"(hi_elem), "f"(lo_elem));
    return r;
}
__device__ __forceinline__ void ldsm4(uint32_t* r, uint32_t addr) {
    asm volatile("ldmatrix.sync.aligned.m8n8.x4.shared.b16 {%0,%1,%2,%3}, [%4];"
                 : "=r"(r[0]), "=r"(r[1]), "=r"(r[2]), "=r"(r[3]) : "r"(addr));
}
__device__ __forceinline__ void mma16816(float* d, const uint32_t* a,
                                         uint32_t b0, uint32_t b1) {
    asm volatile(
        "mma.sync.aligned.m16n8k16.row.col.f32.bf16.bf16.f32 "
        "{%0,%1,%2,%3},{%4,%5,%6,%7},{%8,%9},{%0,%1,%2,%3};"
        : "+f"(d[0]), "+f"(d[1]), "+f"(d[2]), "+f"(d[3])
        : "r"(a[0]), "r"(a[1]), "r"(a[2]), "r"(a[3]), "r"(b0), "r"(b1));
}

// smem layout (float offsets)
#define W_OFF    0        // 16384 fl = 64KB (W fragments, persistent in GEMM1)
#define X_OFF    16384    // 10240 fl region: 2 bufs x 2 planes x 128 x 40 halves
#define CH_OFF   16384    // alias into X region (phase B): 2 x 1280 fl
#define PH_OFF   18944    // alias: 2 x 16*132 fl = 4224
#define ABK_OFF  26624    // 128*33 = 4224 fl (NOT aliased)
#define BIAS_OFF 30848    // 32 fl
#define UB_OFF   30880
#define SMEM_FLOATS 30884
#define SMEM_BYTES (SMEM_FLOATS * 4)

__global__ __launch_bounds__(256, 1) void fused(
    const float* __restrict__ lstm,
    const float* __restrict__ chs,
    const float* __restrict__ bias,
    float* __restrict__ out)
{
    extern __shared__ float S[];
    int* iUblk = (int*)&S[UB_OFF];
    const int tid  = threadIdx.x;
    const int wid  = tid >> 5;
    const int lane = tid & 31;
    const int row0 = blockIdx.x * 128;
    const int b    = blockIdx.x >> 3;
    const float* lbase = lstm + (size_t)row0 * HH;
    const float* cb    = chs + (size_t)b * UU * AA;
    const uint32_t sbase = (uint32_t)__cvta_generic_to_shared(S);
    uint16_t* Xh = (uint16_t*)&S[X_OFF];

    if (tid == 0) *iUblk = 16;
    if (tid < 32) S[BIAS_OFF + tid] = (tid < PP) ? bias[tid] : 0.f;

    // ---- prologue: W fragments (64KB) via cp.async ----
    {
        uint32_t dst = sbase;                 // W_OFF = 0
#pragma unroll
        for (int i = 0; i < 16; ++i) {
            int g = tid + 256 * i;            // 4096 x 16B
            cpa16(dst + (uint32_t)g * 16u, (const char*)g_Wf + g * 16);
        }
        CPA_COMMIT();
    }

    // X staging: per chunk (32 k), warp covers its 16 rows; half-warp = 1 row.
    const int srow = wid * 16 + (lane >> 4);  // +2*it
    const int k2   = lane & 15;               // float2 index within 32-k chunk
    float2 xv[8];

#define LDGX(c) do {                                                           \
    _Pragma("unroll")                                                          \
    for (int it = 0; it < 8; ++it)                                             \
        xv[it] = *(const float2*)(lbase + (size_t)(srow + 2 * it) * HH         \
                                  + (c) * 32 + k2 * 2);                        \
    } while (0)

#define STSX(bsel) do {                                                        \
    _Pragma("unroll")                                                          \
    for (int it = 0; it < 8; ++it) {                                           \
        int r_ = srow + 2 * it;                                                \
        uint32_t p0 = cvt_pack_bf2(xv[it].x, xv[it].y);                        \
        float h0 = __uint_as_float(p0 << 16);                                  \
        float h1 = __uint_as_float(p0 & 0xFFFF0000u);                          \
        uint32_t q0 = cvt_pack_bf2(xv[it].x - h0, xv[it].y - h1);              \
        *(uint32_t*)&Xh[((bsel) * 2 + 0) * 5120 + r_ * 40 + k2 * 2] = p0;      \
        *(uint32_t*)&Xh[((bsel) * 2 + 1) * 5120 + r_ * 40 + k2 * 2] = q0;      \
    } } while (0)

    LDGX(0); STSX(0);
    CPA_WAIT0();
    __syncthreads();

    float acc[2][2][4];
#pragma unroll
    for (int mt = 0; mt < 2; ++mt)
#pragma unroll
        for (int nt = 0; nt < 2; ++nt)
#pragma unroll
            for (int e = 0; e < 4; ++e) acc[mt][nt][e] = 0.f;

    // ---- GEMM1 main loop: 16 chunks x 2 k-tiles ----
#pragma unroll 1
    for (int c = 0; c < 16; ++c) {
        const int buf = c & 1;
        if (c + 1 < 16) LDGX(c + 1);

#pragma unroll
        for (int kt2 = 0; kt2 < 2; ++kt2) {
            const int ktile = c * 2 + kt2;
            uint32_t A[2][2][4];              // [plane][mtile]
#pragma unroll
            for (int pl = 0; pl < 2; ++pl)
#pragma unroll
                for (int mt = 0; mt < 2; ++mt)
                    ldsm4(A[pl][mt],
                          sbase + (uint32_t)((ktile * 4 + pl * 2 + mt) * 512 + lane * 16));
            uint32_t Bf[2][2][2];             // [plane][ntile][b0,b1]
#pragma unroll
            for (int pl = 0; pl < 2; ++pl)
#pragma unroll
                for (int nt = 0; nt < 2; ++nt) {
                    int t  = wid * 16 + nt * 8 + (lane >> 2);
                    int kc = kt2 * 16 + (lane & 3) * 2;
                    const uint16_t* xp = Xh + (buf * 2 + pl) * 5120 + t * 40 + kc;
                    Bf[pl][nt][0] = *(const uint32_t*)xp;
                    Bf[pl][nt][1] = *(const uint32_t*)(xp + 8);
                }
#pragma unroll
            for (int mt = 0; mt < 2; ++mt)
#pragma unroll
                for (int nt = 0; nt < 2; ++nt) {
                    mma16816(acc[mt][nt], A[0][mt], Bf[0][nt][0], Bf[0][nt][1]); // hi*hi
                    mma16816(acc[mt][nt], A[0][mt], Bf[1][nt][0], Bf[1][nt][1]); // hi*lo
                    mma16816(acc[mt][nt], A[1][mt], Bf[0][nt][0], Bf[0][nt][1]); // lo*hi
                }
        }
        if (c + 1 < 16) STSX(buf ^ 1);
        __syncthreads();
    }

    // ---- CH prefetch (X region now free) ----
    {
        uint32_t dst = sbase + (uint32_t)CH_OFF * 4u;
#pragma unroll
        for (int i = 0; i < 3; ++i) {
            int g = tid + 256 * i;
            if (g < 640) cpa16(dst + (uint32_t)g * 16u, cb + g * 4);
        }
        CPA_COMMIT();
    }

    // ---- epilogue: exp(D + bias) -> sABK[t][p] ----
    float* sabk = &S[ABK_OFF];
#pragma unroll
    for (int mt = 0; mt < 2; ++mt)
#pragma unroll
        for (int nt = 0; nt < 2; ++nt)
#pragma unroll
            for (int e = 0; e < 4; ++e) {
                int p = mt * 16 + (lane >> 2) + ((e >= 2) ? 8 : 0);
                int t = wid * 16 + nt * 8 + (lane & 3) * 2 + (e & 1);
                if (p < PP)
                    sabk[t * 33 + p] = __expf(acc[mt][nt][e] + S[BIAS_OFF + p]);
            }
    __syncthreads();

    // ---- phi setup + cutoff ----
    const int tphi = tid & 127, uh = tid >> 7;    // 2 halves x 8 u's per chunk
    float ra[10], rbl[10], rk[10];
    float um = 1.f;
#pragma unroll
    for (int m = 0; m < 10; ++m) {
        float av = sabk[tphi * 33 + m];
        float bv = sabk[tphi * 33 + 10 + m];
        float kv = sabk[tphi * 33 + 20 + m];
        ra[m] = av; rk[m] = kv;
        um = fmaxf(um, kv + sqrtf(40.f / bv));
        rbl[m] = -1.4426950408889634f * bv;       // phi term = a * 2^(rbl*d^2)
    }
    if (uh == 0)
        atomicMax(iUblk, (int)fminf(ceilf(um) + 2.f, (float)UU));
    CPA_WAIT0();
    __syncthreads();
    const int nch = (*iUblk + 15) >> 4;

    // ---- windowed phi + GEMM2 (4t x 10a per thread) ----
    const int tg2 = tid & 31, ag = tid >> 5;
    float accO[4][10];
#pragma unroll
    for (int i = 0; i < 4; ++i)
#pragma unroll
        for (int j = 0; j < 10; ++j) accO[i][j] = 0.f;

#pragma unroll 1
    for (int c = 0; c < nch; ++c) {
        const int kb = c & 1;
        if (c >= 2) {   // rare: stage char chunk c (clamped)
            for (int idx = tid; idx < 1280; idx += 256) {
                int u = idx / 80, a = idx - u * 80;
                int gu = c * 16 + u; if (gu >= UU) gu = UU - 1;
                S[CH_OFF + kb * 1280 + idx] = cb[gu * AA + a];
            }
        }
        float* sphi = &S[PH_OFF + kb * 2112];
#pragma unroll
        for (int r = 0; r < 8; ++r) {
            float uf = (float)(c * 16 + uh * 8 + r);
            float s = 0.f;
#pragma unroll
            for (int m = 0; m < 10; ++m) {
                float d = rk[m] - uf;
                float e; EX2A(e, rbl[m] * d * d);
                s = fmaf(ra[m], e, s);
            }
            sphi[(uh * 8 + r) * 132 + tphi] = s;
        }
        __syncthreads();

        const float* sch = &S[CH_OFF + kb * 1280];
#pragma unroll 4
        for (int u = 0; u < 16; ++u) {
            float4 ph = *(const float4*)&sphi[u * 132 + tg2 * 4];
            const float2* cp2 = (const float2*)&sch[u * 80 + ag * 10];
            float2 c01 = cp2[0], c23 = cp2[1], c45 = cp2[2], c67 = cp2[3], c89 = cp2[4];
            float cc[10] = {c01.x, c01.y, c23.x, c23.y, c45.x,
                            c45.y, c67.x, c67.y, c89.x, c89.y};
#pragma unroll
            for (int j = 0; j < 10; ++j) {
                accO[0][j] = fmaf(ph.x, cc[j], accO[0][j]);
                accO[1][j] = fmaf(ph.y, cc[j], accO[1][j]);
                accO[2][j] = fmaf(ph.z, cc[j], accO[2][j]);
                accO[3][j] = fmaf(ph.w, cc[j], accO[3][j]);
            }
        }
        __syncthreads();
    }

    // ---- store ----
#pragma unroll
    for (int i = 0; i < 4; ++i) {
        float* orow = out + (size_t)(row0 + tg2 * 4 + i) * AA + ag * 10;
#pragma unroll
        for (int j2 = 0; j2 < 5; ++j2)
            *(float2*)&orow[j2 * 2] = make_float2(accO[i][2 * j2], accO[i][2 * j2 + 1]);
    }
}

extern "C" void kernel_launch(void* const* d_in, const int* in_sizes, int n_in,
                              void* d_out, int out_size)
{
    const float* lstm = (const float*)d_in[0];  // [16,1024,512]
    const float* chs  = (const float*)d_in[1];  // [16,600,80]
    const float* W    = (const float*)d_in[2];  // [512,30]
    const float* bias = (const float*)d_in[3];  // [30]
    float* out = (float*)d_out;                 // [16,1024,80]
    (void)in_sizes; (void)n_in; (void)out_size;

    cudaFuncSetAttribute(fused, cudaFuncAttributeMaxDynamicSharedMemorySize, SMEM_BYTES);
    k0_prepW<<<128, 256>>>(W);
    fused<<<128, 256, SMEM_BYTES>>>(lstm, chs, bias, out);
}